// round 14
// baseline (speedup 1.0000x reference)
#include <cuda_runtime.h>
#include <cuda_fp16.h>
#include <cstdint>
#include <cfloat>

// Problem constants
#define Bc 32
#define Dc 256
#define Tc 2048
#define Lc 8
#define Kc 1024
#define Nc (Bc * Tc)
#define OUT_ELEMS ((size_t)Bc * Dc * Tc)
#define IDX_OFF   OUT_ELEMS

// Scratch (no allocations allowed -> __device__ globals)
__device__ float g_resid[(size_t)Nc * Dc];            // 64 MB residual (L2-resident)
__device__ float g_wnorm[Lc * Kc];                    // |W|^2, XLA-exact
__device__ __align__(16) __half g_Wh[(size_t)Lc * Kc * Dc];  // fp16 codebooks (4 MB)

// smem layout (bytes)
#define PA 264             // halves pitch (528B: conflict-free ldmatrix)
#define SM_WW   0          // 1024 f32
#define SM_RR   4096       // 128 f32
#define SM_CAND 4608       // 128*4 int
#define SM_IDX  6656       // 128 int
#define SM_SC   7168       // 256 f32 (rescore partial scores)... 128 used +128
#define SM_CI   8192       // 256 int
#define SM_A    9216       // 128 x 264 half = 67584
#define SM_B0   76800      // 32 x 264 half = 16896
#define SM_B1   93696      // 32 x 264 half = 16896
#define SMEM_TOTAL 110592

__device__ __forceinline__ uint32_t smem_to_u32(const void* p) {
    uint32_t a;
    asm("{ .reg .u64 t; cvta.to.shared.u64 t, %1; cvt.u32.u64 %0, t; }" : "=r"(a) : "l"(p));
    return a;
}
__device__ __forceinline__ void ldsm_x4(uint32_t& r0, uint32_t& r1, uint32_t& r2, uint32_t& r3, uint32_t addr) {
    asm volatile("ldmatrix.sync.aligned.m8n8.x4.shared.b16 {%0,%1,%2,%3}, [%4];"
                 : "=r"(r0), "=r"(r1), "=r"(r2), "=r"(r3) : "r"(addr));
}
__device__ __forceinline__ void mma16816(float* c, uint32_t a0, uint32_t a1, uint32_t a2, uint32_t a3,
                                         uint32_t b0, uint32_t b1) {
    asm volatile("mma.sync.aligned.m16n8k16.row.col.f32.f16.f16.f32 "
                 "{%0,%1,%2,%3}, {%4,%5,%6,%7}, {%8,%9}, {%0,%1,%2,%3};"
                 : "+f"(c[0]), "+f"(c[1]), "+f"(c[2]), "+f"(c[3])
                 : "r"(a0), "r"(a1), "r"(a2), "r"(a3), "r"(b0), "r"(b1));
}

// cp.async-stage B chunk gc (32 codebook rows starting at g_Wh row gc*32).
__device__ __forceinline__ void issue_B(int gc, uint32_t su, int tid) {
    uint32_t dstBase = su + (uint32_t)((gc & 1) ? SM_B1 : SM_B0);
    const __half* src = g_Wh + ((size_t)gc << 5) * Dc;
#pragma unroll
    for (int i = 0; i < 4; ++i) {
        int u = tid + (i << 8);          // 0..1023 units of 16B
        int row = u >> 5;
        int k0  = (u & 31) << 3;
        uint32_t dst = dstBase + (uint32_t)(row * PA + k0) * 2;
        const void* s = src + (size_t)row * Dc + k0;
        asm volatile("cp.async.cg.shared.global [%0], [%1], 16;" :: "r"(dst), "l"(s));
    }
    asm volatile("cp.async.commit_group;" ::: "memory");
}

// ===========================================================================
// Prep kernels
// ===========================================================================
__global__ void wprep_kernel(const float* __restrict__ cb) {
    size_t total = (size_t)Lc * Kc * Dc;
    for (size_t i = (size_t)blockIdx.x * blockDim.x + threadIdx.x; i < total;
         i += (size_t)gridDim.x * blockDim.x)
        g_Wh[i] = __float2half_rn(cb[i]);
}

// wnorm: XLA-exact |W|^2 (validated round 9)
__global__ void wnorm_kernel(const float* __restrict__ cb) {
    __shared__ float s_wp[2][4];
    int t128 = threadIdx.x & 127;
    int g    = threadIdx.x >> 7;
    int lane = threadIdx.x & 31;
    int wIG  = t128 >> 5;
    int row  = blockIdx.x * 2 + g;
    const float* w = cb + (size_t)row * Dc;
    float2 v = *(const float2*)&w[t128 * 2];
    float p = __fadd_rn(__fmul_rn(v.x, v.x), __fmul_rn(v.y, v.y));
#pragma unroll
    for (int off = 16; off; off >>= 1)
        p = __fadd_rn(p, __shfl_down_sync(0xffffffffu, p, off));
    if (lane == 0) s_wp[g][wIG] = p;
    __syncthreads();
    if (t128 == 0) {
        float w0 = s_wp[g][0], w1 = s_wp[g][1], w2 = s_wp[g][2], w3 = s_wp[g][3];
        g_wnorm[row] = __fadd_rn(__fadd_rn(w0, w2), __fadd_rn(w1, w3));
    }
}

__global__ void transpose_in_kernel(const float* __restrict__ x) {
    __shared__ float tile[32][33];
    int b = blockIdx.z, d0 = blockIdx.y * 32, t0 = blockIdx.x * 32;
    int tx = threadIdx.x, ty = threadIdx.y;
#pragma unroll
    for (int j = 0; j < 32; j += 8)
        tile[ty + j][tx] = x[((size_t)b * Dc + d0 + ty + j) * Tc + t0 + tx];
    __syncthreads();
#pragma unroll
    for (int j = 0; j < 32; j += 8)
        g_resid[((size_t)(b * Tc + t0 + ty + j)) * Dc + d0 + tx] = tile[tx][ty + j];
}

__global__ void finalize_kernel(const float* __restrict__ x, float* __restrict__ out) {
    __shared__ float tile[32][33];
    int b = blockIdx.z, d0 = blockIdx.y * 32, t0 = blockIdx.x * 32;
    int tx = threadIdx.x, ty = threadIdx.y;
#pragma unroll
    for (int j = 0; j < 32; j += 8)
        tile[ty + j][tx] = g_resid[((size_t)(b * Tc + t0 + ty + j)) * Dc + d0 + tx];
    __syncthreads();
#pragma unroll
    for (int j = 0; j < 32; j += 8) {
        size_t idx = ((size_t)b * Dc + d0 + ty + j) * Tc + t0 + tx;
        out[idx] = x[idx] - tile[tx][ty + j];
    }
}

// tie-aware insert into ascending top-4 (lower col wins ties)
__device__ __forceinline__ void ins4(float s, int col, float* v, int* c) {
    if (s < v[3] || (s == v[3] && col < c[3])) {
        if (s < v[2] || (s == v[2] && col < c[2])) {
            v[3] = v[2]; c[3] = c[2];
            if (s < v[1] || (s == v[1] && col < c[1])) {
                v[2] = v[1]; c[2] = c[1];
                if (s < v[0] || (s == v[0] && col < c[0])) {
                    v[1] = v[0]; c[1] = c[0]; v[0] = s; c[0] = col;
                } else { v[1] = s; c[1] = col; }
            } else { v[2] = s; c[2] = col; }
        } else { v[3] = s; c[3] = col; }
    }
}

// ===========================================================================
// Fused RVQ kernel. 512 CTAs x 128 rows, 256 threads (8 warps).
// Per layer: HMMA prefilter over 32 double-buffered cp.async B chunks
// -> noisy top-4 -> exact rescore (bit-identical arithmetic) -> fused
// residual update + next-layer rr (XLA-exact order) + next-layer A staging.
// ===========================================================================
__global__ __launch_bounds__(256, 2)
void rvq_fused_kernel(const float* __restrict__ cb, float* __restrict__ dout) {
    extern __shared__ char smem[];
    const uint32_t su = smem_to_u32(smem);
    float* s_ww  = (float*)(smem + SM_WW);
    float* s_rr  = (float*)(smem + SM_RR);
    int*   s_cand = (int*)(smem + SM_CAND);
    int*   s_idx  = (int*)(smem + SM_IDX);
    float* s_sc  = (float*)(smem + SM_SC);
    int*   s_ci  = (int*)(smem + SM_CI);

    const int tid = threadIdx.x;
    const int wid = tid >> 5;
    const int lane = tid & 31;
    const int rowBase = blockIdx.x * 128;

    // ldmatrix lane-fixed addresses (validated round 11)
    const uint32_t aLaneBase = su + SM_A + (uint32_t)(((wid << 4) + (lane & 15)) * PA + ((lane >> 4) << 3)) * 2;
    const uint32_t bLaneOff  = (uint32_t)(((((lane >> 4) << 3) + (lane & 7)) * PA) + (((lane >> 3) & 1) << 3)) * 2;
    const uint32_t bBase0 = su + SM_B0 + bLaneOff;
    const uint32_t bBase1 = su + SM_B1 + bLaneOff;

    // prefetch first B chunk; overlaps with prologue below
    issue_B(0, su, tid);

    // ---- prologue: stage A (fp16) + rr (XLA-exact) from initial residual --
    // 4-virtual-warp trick: lane carries the 4 warp-partials of one row; the
    // shfl tree order is bitwise-identical to the validated 128-thread form.
#pragma unroll 1
    for (int p = 0; p < 16; ++p) {
        int row = (p << 3) + wid;
        const float* rrow = g_resid + (size_t)(rowBase + row) * Dc;
        float pv[4];
#pragma unroll
        for (int v = 0; v < 4; ++v) {
            int o = (v << 6) + (lane << 1);
            float2 r = *(const float2*)&rrow[o];
            pv[v] = __fadd_rn(__fmul_rn(r.x, r.x), __fmul_rn(r.y, r.y));
            *(__half2*)(smem + SM_A + (size_t)(row * PA + o) * 2) = __floats2half2_rn(r.x, r.y);
        }
#pragma unroll
        for (int off = 16; off; off >>= 1)
#pragma unroll
            for (int v = 0; v < 4; ++v)
                pv[v] = __fadd_rn(pv[v], __shfl_down_sync(0xffffffffu, pv[v], off));
        if (lane == 0)
            s_rr[row] = __fadd_rn(__fadd_rn(pv[0], pv[2]), __fadd_rn(pv[1], pv[3]));
    }

    for (int l = 0; l < Lc; ++l) {
        const int lRow = l * Kc;
        *(float4*)&s_ww[tid * 4] = *(const float4*)(g_wnorm + lRow + tid * 4);

        // per-row noisy top-4 (2 rows/thread: rows 16*wid + (lane>>2), +8)
        float tv0[4], tv1[4];
        int   tc0[4], tc1[4];
#pragma unroll
        for (int j = 0; j < 4; ++j) {
            tv0[j] = FLT_MAX; tv1[j] = FLT_MAX; tc0[j] = 1 << 30; tc1[j] = 1 << 30;
        }

        // ---- 32 chunks of 32 codewords, double-buffered cp.async ----------
        for (int ch = 0; ch < 32; ++ch) {
            const int gc = (l << 5) + ch;
            asm volatile("cp.async.wait_group 0;" ::: "memory");
            __syncthreads();                       // buf[gc&1] ready; prior reads done
            if (gc + 1 < 256) issue_B(gc + 1, su, tid);

            const uint32_t bB = (gc & 1) ? bBase1 : bBase0;
            float acc[4][4];
#pragma unroll
            for (int n = 0; n < 4; ++n)
#pragma unroll
                for (int j = 0; j < 4; ++j) acc[n][j] = 0.f;

#pragma unroll
            for (int ks = 0; ks < 16; ++ks) {
                uint32_t a0, a1, a2, a3;
                ldsm_x4(a0, a1, a2, a3, aLaneBase + ks * 32);
                uint32_t b0, b1, b2, b3;
                ldsm_x4(b0, b1, b2, b3, bB + ks * 32);
                mma16816(acc[0], a0, a1, a2, a3, b0, b1);
                mma16816(acc[1], a0, a1, a2, a3, b2, b3);
                uint32_t c0, c1, c2, c3;
                ldsm_x4(c0, c1, c2, c3, bB + (uint32_t)(16 * PA) * 2 + ks * 32);
                mma16816(acc[2], a0, a1, a2, a3, c0, c1);
                mma16816(acc[3], a0, a1, a2, a3, c2, c3);
            }

            // epilogue: fold into top-4
#pragma unroll
            for (int n = 0; n < 4; ++n) {
                int cbase = (ch << 5) + (n << 3) + ((lane & 3) << 1);
                float ww0 = s_ww[cbase], ww1 = s_ww[cbase + 1];
                ins4(fmaf(-2.f, acc[n][0], ww0), cbase,     tv0, tc0);
                ins4(fmaf(-2.f, acc[n][1], ww1), cbase + 1, tv0, tc0);
                ins4(fmaf(-2.f, acc[n][2], ww0), cbase,     tv1, tc1);
                ins4(fmaf(-2.f, acc[n][3], ww1), cbase + 1, tv1, tc1);
            }
        }

        // ---- quad gather: lane q0 of each quad merges 3 partners ----------
#pragma unroll
        for (int src = 1; src < 4; ++src) {
#pragma unroll
            for (int j = 0; j < 4; ++j) {
                float pv0 = __shfl_sync(0xffffffffu, tv0[j], (lane & ~3) + src);
                int   pc0 = __shfl_sync(0xffffffffu, tc0[j], (lane & ~3) + src);
                float pv1 = __shfl_sync(0xffffffffu, tv1[j], (lane & ~3) + src);
                int   pc1 = __shfl_sync(0xffffffffu, tc1[j], (lane & ~3) + src);
                if ((lane & 3) == 0) {
                    ins4(pv0, pc0, tv0, tc0);
                    ins4(pv1, pc1, tv1, tc1);
                }
            }
        }
        if ((lane & 3) == 0) {
            int rA = (wid << 4) + (lane >> 2);
#pragma unroll
            for (int j = 0; j < 4; ++j) {
                s_cand[rA * 4 + j]       = tc0[j];
                s_cand[(rA + 8) * 4 + j] = tc1[j];
            }
        }
        __syncthreads();

        // ---- exact rescore: 256 threads, 2 candidates each ---------------
        {
            int row = tid & 127;
            int hf  = tid >> 7;
            int ca  = s_cand[row * 4 + hf * 2];
            int cb2 = s_cand[row * 4 + hf * 2 + 1];
            const float* rrow = g_resid + (size_t)(rowBase + row) * Dc;
            const float* wA = cb + (size_t)(lRow + ca)  * Dc;
            const float* wB = cb + (size_t)(lRow + cb2) * Dc;
            float da = 0.f, db = 0.f;
#pragma unroll 8
            for (int k = 0; k < Dc; ++k) {     // serial ascending FFMA == cuBLAS
                float r = rrow[k];
                da = fmaf(r, wA[k], da);
                db = fmaf(r, wB[k], db);
            }
            float rr = s_rr[row];
            float sa = __fadd_rn(__fadd_rn(rr, __fmul_rn(-2.f, da)), s_ww[ca]);
            float sb = __fadd_rn(__fadd_rn(rr, __fmul_rn(-2.f, db)), s_ww[cb2]);
            float ls; int li;
            if (sb < sa || (sb == sa && cb2 < ca)) { ls = sb; li = cb2; }
            else                                   { ls = sa; li = ca;  }
            s_sc[tid] = ls; s_ci[tid] = li;
            __syncthreads();
            if (tid < 128) {
                float os = s_sc[tid + 128];
                int   oi = s_ci[tid + 128];
                int sel = (os < ls || (os == ls && oi < li)) ? oi : li;
                s_idx[row] = sel;
                int n = rowBase + row;
                int b = n >> 11;
                int t = n & 2047;
                dout[IDX_OFF + ((size_t)b * Lc + l) * Tc + t] = (float)sel;
            }
            __syncthreads();
        }

        // ---- fused: residual update + next-layer rr + next-layer A stage --
        {
            const bool doAux = (l < Lc - 1);
#pragma unroll 1
            for (int p = 0; p < 16; ++p) {
                int row = (p << 3) + wid;
                float* rrow = g_resid + (size_t)(rowBase + row) * Dc;
                const float* wrow = cb + (size_t)(lRow + s_idx[row]) * Dc;
                float2 rv[4];
#pragma unroll
                for (int v = 0; v < 4; ++v) {
                    int o = (v << 6) + (lane << 1);
                    float2 r = *(float2*)&rrow[o];
                    float2 w = *(const float2*)&wrow[o];
                    r.x -= w.x; r.y -= w.y;           // exact fp32 == reference
                    *(float2*)&rrow[o] = r;
                    rv[v] = r;
                }
                if (doAux) {
                    float pv[4];
#pragma unroll
                    for (int v = 0; v < 4; ++v) {
                        int o = (v << 6) + (lane << 1);
                        pv[v] = __fadd_rn(__fmul_rn(rv[v].x, rv[v].x), __fmul_rn(rv[v].y, rv[v].y));
                        *(__half2*)(smem + SM_A + (size_t)(row * PA + o) * 2) =
                            __floats2half2_rn(rv[v].x, rv[v].y);
                    }
#pragma unroll
                    for (int off = 16; off; off >>= 1)
#pragma unroll
                        for (int v = 0; v < 4; ++v)
                            pv[v] = __fadd_rn(pv[v], __shfl_down_sync(0xffffffffu, pv[v], off));
                    if (lane == 0)
                        s_rr[row] = __fadd_rn(__fadd_rn(pv[0], pv[2]), __fadd_rn(pv[1], pv[3]));
                }
            }
            __syncthreads();
        }
    }
}

// ---------------------------------------------------------------------------
extern "C" void kernel_launch(void* const* d_in, const int* in_sizes, int n_in,
                              void* d_out, int out_size) {
    const float* x  = (const float*)d_in[0];
    const float* cb = (const float*)d_in[1];
    if (n_in >= 2 && in_sizes[0] == Lc * Kc * Dc && in_sizes[1] == Bc * Dc * Tc) {
        const float* tmp = x; x = cb; cb = tmp;
    }
    float* out = (float*)d_out;

    static int smem_set = 0;
    if (!smem_set) {
        cudaFuncSetAttribute(rvq_fused_kernel, cudaFuncAttributeMaxDynamicSharedMemorySize, SMEM_TOTAL);
        smem_set = 1;
    }

    // 1. codebook prep: fp16 copy + XLA-exact norms
    wprep_kernel<<<512, 256>>>(cb);
    wnorm_kernel<<<(Lc * Kc) / 2, 256>>>(cb);

    // 2. x -> residual (N, D)
    {
        dim3 grid(Tc / 32, Dc / 32, Bc);
        dim3 block(32, 8);
        transpose_in_kernel<<<grid, block>>>(x);
    }

    // 3. all 8 layers fused
    rvq_fused_kernel<<<Nc / 128, 256, SMEM_TOTAL>>>(cb, out);

    // 4. out = x - final residual
    {
        dim3 grid(Tc / 32, Dc / 32, Bc);
        dim3 block(32, 8);
        finalize_kernel<<<grid, block>>>(x, out);
    }
}

// round 17
// speedup vs baseline: 1.5349x; 1.5349x over previous
#include <cuda_runtime.h>
#include <cuda_fp16.h>
#include <cstdint>
#include <cfloat>

// Problem constants
#define Bc 32
#define Dc 256
#define Tc 2048
#define Lc 8
#define Kc 1024
#define Nc (Bc * Tc)
#define OUT_ELEMS ((size_t)Bc * Dc * Tc)
#define IDX_OFF   OUT_ELEMS
#define ROWS 64                      // rows per CTA

// Scratch (no allocations allowed -> __device__ globals)
__device__ float g_resid[(size_t)Nc * Dc];            // 64 MB residual (L2-resident)
__device__ float g_wnorm[Lc * Kc];                    // |W|^2, XLA-exact
__device__ __align__(16) __half g_Wh[(size_t)Lc * Kc * Dc];  // fp16 codebooks (4 MB)

// smem layout (bytes) — 77,312 total -> 3 CTAs/SM (3*77312 = 231936 <= 233472)
#define PA 264             // halves pitch (528B: conflict-free ldmatrix)
#define SM_WW   0          // 1024 f32                      4096
#define SM_RR   4096       // 64 f32                        256
#define SM_WLV  4352       // 64*2*4 f32 warp-list scores   2048
#define SM_WLC  6400       // 64*2*4 int warp-list cols     2048
// Rescore scratch aliases the warp-list region (disjoint lifetime, barrier-
// separated: warp lists are dead once s_cand is built).
#define SM_SC   4352       // 256 f32 (rescore scores)
#define SM_CI   5376       // 256 int (rescore cols)
#define SM_CAND 8448       // 64*4 int                      1024
#define SM_IDX  9472       // 64 int                        256
#define SM_A    9728       // 64 x 264 half                 33792
#define SM_B    43520      // 64 x 264 half                 33792
#define SMEM_TOTAL 77312

__device__ __forceinline__ uint32_t smem_to_u32(const void* p) {
    uint32_t a;
    asm("{ .reg .u64 t; cvta.to.shared.u64 t, %1; cvt.u32.u64 %0, t; }" : "=r"(a) : "l"(p));
    return a;
}
__device__ __forceinline__ void ldsm_x4(uint32_t& r0, uint32_t& r1, uint32_t& r2, uint32_t& r3, uint32_t addr) {
    asm volatile("ldmatrix.sync.aligned.m8n8.x4.shared.b16 {%0,%1,%2,%3}, [%4];"
                 : "=r"(r0), "=r"(r1), "=r"(r2), "=r"(r3) : "r"(addr));
}
__device__ __forceinline__ void mma16816(float* c, uint32_t a0, uint32_t a1, uint32_t a2, uint32_t a3,
                                         uint32_t b0, uint32_t b1) {
    asm volatile("mma.sync.aligned.m16n8k16.row.col.f32.f16.f16.f32 "
                 "{%0,%1,%2,%3}, {%4,%5,%6,%7}, {%8,%9}, {%0,%1,%2,%3};"
                 : "+f"(c[0]), "+f"(c[1]), "+f"(c[2]), "+f"(c[3])
                 : "r"(a0), "r"(a1), "r"(a2), "r"(a3), "r"(b0), "r"(b1));
}

// ===========================================================================
// Prep kernels (unchanged, validated)
// ===========================================================================
__global__ void wprep_kernel(const float* __restrict__ cb) {
    size_t total = (size_t)Lc * Kc * Dc;
    for (size_t i = (size_t)blockIdx.x * blockDim.x + threadIdx.x; i < total;
         i += (size_t)gridDim.x * blockDim.x)
        g_Wh[i] = __float2half_rn(cb[i]);
}

__global__ void wnorm_kernel(const float* __restrict__ cb) {
    __shared__ float s_wp[2][4];
    int t128 = threadIdx.x & 127;
    int g    = threadIdx.x >> 7;
    int lane = threadIdx.x & 31;
    int wIG  = t128 >> 5;
    int row  = blockIdx.x * 2 + g;
    const float* w = cb + (size_t)row * Dc;
    float2 v = *(const float2*)&w[t128 * 2];
    float p = __fadd_rn(__fmul_rn(v.x, v.x), __fmul_rn(v.y, v.y));
#pragma unroll
    for (int off = 16; off; off >>= 1)
        p = __fadd_rn(p, __shfl_down_sync(0xffffffffu, p, off));
    if (lane == 0) s_wp[g][wIG] = p;
    __syncthreads();
    if (t128 == 0) {
        float w0 = s_wp[g][0], w1 = s_wp[g][1], w2 = s_wp[g][2], w3 = s_wp[g][3];
        g_wnorm[row] = __fadd_rn(__fadd_rn(w0, w2), __fadd_rn(w1, w3));
    }
}

__global__ void transpose_in_kernel(const float* __restrict__ x) {
    __shared__ float tile[32][33];
    int b = blockIdx.z, d0 = blockIdx.y * 32, t0 = blockIdx.x * 32;
    int tx = threadIdx.x, ty = threadIdx.y;
#pragma unroll
    for (int j = 0; j < 32; j += 8)
        tile[ty + j][tx] = x[((size_t)b * Dc + d0 + ty + j) * Tc + t0 + tx];
    __syncthreads();
#pragma unroll
    for (int j = 0; j < 32; j += 8)
        g_resid[((size_t)(b * Tc + t0 + ty + j)) * Dc + d0 + tx] = tile[tx][ty + j];
}

__global__ void finalize_kernel(const float* __restrict__ x, float* __restrict__ out) {
    __shared__ float tile[32][33];
    int b = blockIdx.z, d0 = blockIdx.y * 32, t0 = blockIdx.x * 32;
    int tx = threadIdx.x, ty = threadIdx.y;
#pragma unroll
    for (int j = 0; j < 32; j += 8)
        tile[ty + j][tx] = g_resid[((size_t)(b * Tc + t0 + ty + j)) * Dc + d0 + tx];
    __syncthreads();
#pragma unroll
    for (int j = 0; j < 32; j += 8) {
        size_t idx = ((size_t)b * Dc + d0 + ty + j) * Tc + t0 + tx;
        out[idx] = x[idx] - tile[tx][ty + j];
    }
}

// Hot-path insert: strict < only. Cols processed ascending within a thread,
// so equal scores keep the earlier (= lower) col — exact first-min semantics.
__device__ __forceinline__ void ins4f(float s, int col, float* v, int* c) {
    if (s < v[3]) {
        if (s < v[2]) {
            v[3] = v[2]; c[3] = c[2];
            if (s < v[1]) {
                v[2] = v[1]; c[2] = c[1];
                if (s < v[0]) { v[1] = v[0]; c[1] = c[0]; v[0] = s; c[0] = col; }
                else          { v[1] = s; c[1] = col; }
            } else { v[2] = s; c[2] = col; }
        } else { v[3] = s; c[3] = col; }
    }
}
// Tie-aware insert for cross-lane/cross-warp merges (lower col wins ties).
__device__ __forceinline__ void ins4t(float s, int col, float* v, int* c) {
    if (s < v[3] || (s == v[3] && col < c[3])) {
        if (s < v[2] || (s == v[2] && col < c[2])) {
            v[3] = v[2]; c[3] = c[2];
            if (s < v[1] || (s == v[1] && col < c[1])) {
                v[2] = v[1]; c[2] = c[1];
                if (s < v[0] || (s == v[0] && col < c[0])) {
                    v[1] = v[0]; c[1] = c[0]; v[0] = s; c[0] = col;
                } else { v[1] = s; c[1] = col; }
            } else { v[2] = s; c[2] = col; }
        } else { v[3] = s; c[3] = col; }
    }
}

// ===========================================================================
// Fused RVQ kernel. 1024 CTAs x 64 rows, 256 threads (8 warps), 3 CTAs/SM.
// Warp grid: 4 M-tiles (16 rows) x 2 N-halves (32 cols). Per layer:
// HMMA prefilter over 16 sync-staged 64-col chunks -> noisy top-4 (quad merge
// + cross-warp merge) -> exact rescore (bit-identical arithmetic) -> fused
// residual update + next-layer rr (XLA-exact) + next-layer A staging.
// ===========================================================================
__global__ __launch_bounds__(256, 3)
void rvq_fused_kernel(const float* __restrict__ cb, float* __restrict__ dout) {
    extern __shared__ char smem[];
    const uint32_t su = smem_to_u32(smem);
    float* s_ww  = (float*)(smem + SM_WW);
    float* s_rr  = (float*)(smem + SM_RR);
    float* s_wlv = (float*)(smem + SM_WLV);
    int*   s_wlc = (int*)(smem + SM_WLC);
    float* s_sc  = (float*)(smem + SM_SC);
    int*   s_ci  = (int*)(smem + SM_CI);
    int*   s_cand = (int*)(smem + SM_CAND);
    int*   s_idx  = (int*)(smem + SM_IDX);

    const int tid = threadIdx.x;
    const int wid = tid >> 5;
    const int lane = tid & 31;
    const int widm = wid & 3;        // M tile (16 rows)
    const int widn = wid >> 2;       // N half (32 cols)
    const int rowBase = blockIdx.x * ROWS;

    // ldmatrix lane-fixed addresses (fragment scheme validated round 11)
    const uint32_t aLaneBase = su + SM_A +
        (uint32_t)(((widm << 4) + (lane & 15)) * PA + ((lane >> 4) << 3)) * 2;
    const uint32_t bLaneBase = su + SM_B +
        (uint32_t)(((widn << 5) + (((lane >> 4) << 3) + (lane & 7))) * PA + (((lane >> 3) & 1) << 3)) * 2;

    // ---- prologue: stage A (fp16) + rr (XLA-exact) from initial residual --
#pragma unroll 1
    for (int p = 0; p < 8; ++p) {
        int row = (p << 3) + wid;
        const float* rrow = g_resid + (size_t)(rowBase + row) * Dc;
        float pv[4];
#pragma unroll
        for (int v = 0; v < 4; ++v) {
            int o = (v << 6) + (lane << 1);
            float2 r = *(const float2*)&rrow[o];
            pv[v] = __fadd_rn(__fmul_rn(r.x, r.x), __fmul_rn(r.y, r.y));
            *(__half2*)(smem + SM_A + (size_t)(row * PA + o) * 2) = __floats2half2_rn(r.x, r.y);
        }
#pragma unroll
        for (int off = 16; off; off >>= 1)
#pragma unroll
            for (int v = 0; v < 4; ++v)
                pv[v] = __fadd_rn(pv[v], __shfl_down_sync(0xffffffffu, pv[v], off));
        if (lane == 0)
            s_rr[row] = __fadd_rn(__fadd_rn(pv[0], pv[2]), __fadd_rn(pv[1], pv[3]));
    }

    for (int l = 0; l < Lc; ++l) {
        const int lRow = l * Kc;
        *(float4*)&s_ww[tid * 4] = *(const float4*)(g_wnorm + lRow + tid * 4);

        // per-row noisy top-4 (2 rows/thread: rows 16*widm + (lane>>2), +8)
        float tv0[4], tv1[4];
        int   tc0[4], tc1[4];
#pragma unroll
        for (int j = 0; j < 4; ++j) {
            tv0[j] = FLT_MAX; tv1[j] = FLT_MAX; tc0[j] = 1 << 30; tc1[j] = 1 << 30;
        }

        // ---- 16 chunks of 64 codewords (synchronous staging) --------------
        for (int ch = 0; ch < 16; ++ch) {
            // stage B chunk: 64 rows x 256 halves from g_Wh
#pragma unroll
            for (int i = 0; i < 8; ++i) {
                int u = tid + (i << 8);      // 2048 units of 8 halves
                int row = u >> 5;
                int k0  = (u & 31) << 3;
                uint4 v = *(const uint4*)(g_Wh + ((size_t)(lRow + (ch << 6) + row)) * Dc + k0);
                *(uint4*)(smem + SM_B + (size_t)(row * PA + k0) * 2) = v;
            }
            __syncthreads();

            float acc[4][4];
#pragma unroll
            for (int n = 0; n < 4; ++n)
#pragma unroll
                for (int j = 0; j < 4; ++j) acc[n][j] = 0.f;

#pragma unroll 4
            for (int ks = 0; ks < 16; ++ks) {
                uint32_t a0, a1, a2, a3;
                ldsm_x4(a0, a1, a2, a3, aLaneBase + ks * 32);
#pragma unroll
                for (int p = 0; p < 2; ++p) {
                    uint32_t r0, r1, r2, r3;
                    ldsm_x4(r0, r1, r2, r3, bLaneBase + (uint32_t)(p * 16 * PA) * 2 + ks * 32);
                    mma16816(acc[2 * p],     a0, a1, a2, a3, r0, r1);
                    mma16816(acc[2 * p + 1], a0, a1, a2, a3, r2, r3);
                }
            }

            // epilogue: fold into per-thread top-4 (warp covers cols 32*widn..)
#pragma unroll
            for (int n = 0; n < 4; ++n) {
                int cbase = (ch << 6) + (widn << 5) + (n << 3) + ((lane & 3) << 1);
                float ww0 = s_ww[cbase], ww1 = s_ww[cbase + 1];
                ins4f(fmaf(-2.f, acc[n][0], ww0), cbase,     tv0, tc0);
                ins4f(fmaf(-2.f, acc[n][1], ww1), cbase + 1, tv0, tc0);
                ins4f(fmaf(-2.f, acc[n][2], ww0), cbase,     tv1, tc1);
                ins4f(fmaf(-2.f, acc[n][3], ww1), cbase + 1, tv1, tc1);
            }
            __syncthreads();
        }

        // ---- quad gather: lane q0 of each quad merges 3 partners ----------
#pragma unroll
        for (int src = 1; src < 4; ++src) {
#pragma unroll
            for (int j = 0; j < 4; ++j) {
                float pv0 = __shfl_sync(0xffffffffu, tv0[j], (lane & ~3) + src);
                int   pc0 = __shfl_sync(0xffffffffu, tc0[j], (lane & ~3) + src);
                float pv1 = __shfl_sync(0xffffffffu, tv1[j], (lane & ~3) + src);
                int   pc1 = __shfl_sync(0xffffffffu, tc1[j], (lane & ~3) + src);
                if ((lane & 3) == 0) {
                    ins4t(pv0, pc0, tv0, tc0);
                    ins4t(pv1, pc1, tv1, tc1);
                }
            }
        }
        // write per-warp top-4 (score + col) into dedicated warp-list region
        if ((lane & 3) == 0) {
            int rA = (widm << 4) + (lane >> 2);      // 0..15 within M tile
#pragma unroll
            for (int j = 0; j < 4; ++j) {
                s_wlv[(rA * 2 + widn) * 4 + j] = tv0[j];
                s_wlc[(rA * 2 + widn) * 4 + j] = tc0[j];
                s_wlv[((rA + 8) * 2 + widn) * 4 + j] = tv1[j];
                s_wlc[((rA + 8) * 2 + widn) * 4 + j] = tc1[j];
            }
        }
        __syncthreads();

        // ---- cross-warp merge: threads 0..63 merge the two warp lists -----
        if (tid < ROWS) {
            float v[4]; int c[4];
#pragma unroll
            for (int j = 0; j < 4; ++j) { v[j] = s_wlv[(tid * 2) * 4 + j]; c[j] = s_wlc[(tid * 2) * 4 + j]; }
#pragma unroll
            for (int j = 0; j < 4; ++j) ins4t(s_wlv[(tid * 2 + 1) * 4 + j], s_wlc[(tid * 2 + 1) * 4 + j], v, c);
#pragma unroll
            for (int j = 0; j < 4; ++j) s_cand[tid * 4 + j] = c[j];
        }
        __syncthreads();      // warp lists dead from here; s_sc/s_ci may alias

        // ---- exact rescore: 256 threads, 1 candidate each -----------------
        {
            int row = tid >> 2;
            int j   = tid & 3;
            int cc  = s_cand[row * 4 + j];
            const float* rrow = g_resid + (size_t)(rowBase + row) * Dc;
            const float* wr = cb + (size_t)(lRow + cc) * Dc;
            float d = 0.f;
#pragma unroll 8
            for (int k = 0; k < Dc; ++k)       // serial ascending FFMA == cuBLAS
                d = fmaf(rrow[k], wr[k], d);
            float s = __fadd_rn(__fadd_rn(s_rr[row], __fmul_rn(-2.f, d)), s_ww[cc]);
            __syncthreads();                   // all s_cand reads done before aliasing write
            s_sc[tid] = s; s_ci[tid] = cc;
            __syncthreads();
            if (tid < ROWS) {
                float bs = s_sc[tid * 4]; int bi = s_ci[tid * 4];
#pragma unroll
                for (int q = 1; q < 4; ++q) {
                    float os = s_sc[tid * 4 + q];
                    int   oi = s_ci[tid * 4 + q];
                    if (os < bs || (os == bs && oi < bi)) { bs = os; bi = oi; }
                }
                s_idx[tid] = bi;
                int n = rowBase + tid;
                int b = n >> 11;
                int t = n & 2047;
                dout[IDX_OFF + ((size_t)b * Lc + l) * Tc + t] = (float)bi;
            }
            __syncthreads();
        }

        // ---- fused: residual update + next-layer rr + next-layer A stage --
        {
            const bool doAux = (l < Lc - 1);
#pragma unroll 1
            for (int p = 0; p < 8; ++p) {
                int row = (p << 3) + wid;
                float* rrow = g_resid + (size_t)(rowBase + row) * Dc;
                const float* wrow = cb + (size_t)(lRow + s_idx[row]) * Dc;
                float2 rv[4];
#pragma unroll
                for (int v = 0; v < 4; ++v) {
                    int o = (v << 6) + (lane << 1);
                    float2 r = *(float2*)&rrow[o];
                    float2 w = *(const float2*)&wrow[o];
                    r.x -= w.x; r.y -= w.y;           // exact fp32 == reference
                    *(float2*)&rrow[o] = r;
                    rv[v] = r;
                }
                if (doAux) {
                    float pv[4];
#pragma unroll
                    for (int v = 0; v < 4; ++v) {
                        int o = (v << 6) + (lane << 1);
                        pv[v] = __fadd_rn(__fmul_rn(rv[v].x, rv[v].x), __fmul_rn(rv[v].y, rv[v].y));
                        *(__half2*)(smem + SM_A + (size_t)(row * PA + o) * 2) =
                            __floats2half2_rn(rv[v].x, rv[v].y);
                    }
#pragma unroll
                    for (int off = 16; off; off >>= 1)
#pragma unroll
                        for (int v = 0; v < 4; ++v)
                            pv[v] = __fadd_rn(pv[v], __shfl_down_sync(0xffffffffu, pv[v], off));
                    if (lane == 0)
                        s_rr[row] = __fadd_rn(__fadd_rn(pv[0], pv[2]), __fadd_rn(pv[1], pv[3]));
                }
            }
            __syncthreads();
        }
    }
}

// ---------------------------------------------------------------------------
extern "C" void kernel_launch(void* const* d_in, const int* in_sizes, int n_in,
                              void* d_out, int out_size) {
    const float* x  = (const float*)d_in[0];
    const float* cb = (const float*)d_in[1];
    if (n_in >= 2 && in_sizes[0] == Lc * Kc * Dc && in_sizes[1] == Bc * Dc * Tc) {
        const float* tmp = x; x = cb; cb = tmp;
    }
    float* out = (float*)d_out;

    static int smem_set = 0;
    if (!smem_set) {
        cudaFuncSetAttribute(rvq_fused_kernel, cudaFuncAttributeMaxDynamicSharedMemorySize, SMEM_TOTAL);
        smem_set = 1;
    }

    // 1. codebook prep: fp16 copy + XLA-exact norms
    wprep_kernel<<<512, 256>>>(cb);
    wnorm_kernel<<<(Lc * Kc) / 2, 256>>>(cb);

    // 2. x -> residual (N, D)
    {
        dim3 grid(Tc / 32, Dc / 32, Bc);
        dim3 block(32, 8);
        transpose_in_kernel<<<grid, block>>>(x);
    }

    // 3. all 8 layers fused
    rvq_fused_kernel<<<Nc / ROWS, 256, SMEM_TOTAL>>>(cb, out);

    // 4. out = x - final residual
    {
        dim3 grid(Tc / 32, Dc / 32, Bc);
        dim3 block(32, 8);
        finalize_kernel<<<grid, block>>>(x, out);
    }
}